// round 4
// baseline (speedup 1.0000x reference)
#include <cuda_runtime.h>
#include <cuda_bf16.h>

#define IMG_W 416
#define IMG_H 416
#define NCH   3
#define TPB   256

// ---------------------------------------------------------------------------
// Kernel 1: pure zero-fill of the output (the ~99.7% case) at max write BW.
// ---------------------------------------------------------------------------
__global__ void __launch_bounds__(TPB)
fill_kernel(float4* __restrict__ out, int n4) {
    int i = blockIdx.x * TPB + threadIdx.x;
    const int stride = gridDim.x * TPB;
    const float4 z = make_float4(0.f, 0.f, 0.f, 0.f);
    // unrolled grid-stride: 4 independent stores in flight per iteration
    for (; i + 3 * stride < n4; i += 4 * stride) {
        out[i]              = z;
        out[i + stride]     = z;
        out[i + 2 * stride] = z;
        out[i + 3 * stride] = z;
    }
    for (; i < n4; i += stride) out[i] = z;
}

// ---------------------------------------------------------------------------
// Kernel 2: one block per sample. Compute theta, invert the affine map to get
// the tiny output-space bbox that can receive nonzero values, and bilinear-
// sample only those pixels (typ. ~35x35 of 416x416).
// ---------------------------------------------------------------------------
__global__ void __launch_bounds__(TPB)
patch_kernel(const float* __restrict__ img,
             const float* __restrict__ bb,
             const float* __restrict__ angle,
             const int*   __restrict__ pos_ptr,
             float* __restrict__ out) {
    __shared__ float th[6];
    __shared__ int   box[4];   // x0, y0, bw, bh

    const int n = blockIdx.x;

    if (threadIdx.x == 0) {
        float patch_ori = 300.0f;
        if (pos_ptr) {
            int pi = pos_ptr[0];
            patch_ori = (pi > 0 && pi < 1000000) ? (float)pi : __int_as_float(pi);
        }
        float x1 = bb[n * 6 + 0];
        float y1 = bb[n * 6 + 1];
        float x2 = bb[n * 6 + 2];
        float y2 = bb[n * 6 + 3];

        float bwv = (x2 - x1) * (float)IMG_W;
        float bhv = (y2 - y1) * (float)IMG_H;
        float cx  = (x1 + x2) * 0.5f;
        float cy  = (y1 + y2) * 0.5f - (y2 - y1) * 0.1f;
        float tx  = (0.5f - cx) * 2.0f;
        float ty  = (0.5f - cy) * 2.0f;
        float target = 0.2f * sqrtf(bwv * bwv + bhv * bhv);
        float scale  = __fdiv_rn(target, patch_ori);

        float a = angle[n];
        float s = sinf(a);
        float c = cosf(a);

        float t00 = __fdiv_rn(c, scale);
        float t01 = __fdiv_rn(s, scale);
        float t02 = __fdiv_rn(tx * c + ty * s, scale);
        float t10 = __fdiv_rn(-s, scale);
        float t11 = __fdiv_rn(c, scale);
        float t12 = __fdiv_rn(-tx * s + ty * c, scale);
        th[0] = t00; th[1] = t01; th[2] = t02;
        th[3] = t10; th[4] = t11; th[5] = t12;

        // Pixel-space map: ix = t00*x + t01*y + cx2 ; iy = t10*x + t11*y + cy2
        float cx2 = 207.5f - 207.5f * t00 - 207.5f * t01 + 208.0f * t02;
        float cy2 = 207.5f - 207.5f * t10 - 207.5f * t11 + 208.0f * t12;

        // Preimage of (ix,iy) in [-1,416]^2: invert the 2x2 map, take corner bbox.
        float det  = t00 * t11 - t01 * t10;         // = 1/scale^2, >= ~8
        float rdet = __fdiv_rn(1.0f, det);
        float xmin = 1e9f, xmax = -1e9f, ymin = 1e9f, ymax = -1e9f;
#pragma unroll
        for (int k = 0; k < 4; k++) {
            float u  = (k & 1) ? 416.0f : -1.0f;
            float v  = (k & 2) ? 416.0f : -1.0f;
            float du = u - cx2;
            float dv = v - cy2;
            float px = (t11 * du - t01 * dv) * rdet;
            float py = (t00 * dv - t10 * du) * rdet;
            xmin = fminf(xmin, px); xmax = fmaxf(xmax, px);
            ymin = fminf(ymin, py); ymax = fmaxf(ymax, py);
        }
        int x0 = max(0, (int)floorf(xmin) - 2);
        int y0 = max(0, (int)floorf(ymin) - 2);
        int x1i = min(IMG_W - 1, (int)ceilf(xmax) + 2);
        int y1i = min(IMG_H - 1, (int)ceilf(ymax) + 2);
        box[0] = x0;
        box[1] = y0;
        box[2] = (x1i >= x0) ? (x1i - x0 + 1) : 0;
        box[3] = (y1i >= y0) ? (y1i - y0 + 1) : 0;
    }
    __syncthreads();

    const float t00 = th[0], t01 = th[1], t02 = th[2];
    const float t10 = th[3], t11 = th[4], t12 = th[5];
    const int bx = box[0], by = box[1], bw = box[2], bh = box[3];
    const int total = bw * bh;
    if (total == 0) return;

    const int cs = IMG_H * IMG_W;
    const float* base = img + n * NCH * cs;
    float* obase = out + (size_t)n * NCH * cs;

    for (int idx = threadIdx.x; idx < total; idx += TPB) {
        const int xx = bx + idx % bw;
        const int yy = by + idx / bw;

        // Same arithmetic as the verified full kernel (rel_err 1.1e-4):
        const float ysv = __fdiv_rn(2.0f * (float)yy + 1.0f, (float)IMG_W) - 1.0f;
        const float Cx = fmaf(208.0f, fmaf(t01, ysv, t02), fmaf(-207.5f, t00, 207.5f));
        const float Cy = fmaf(208.0f, fmaf(t11, ysv, t12), fmaf(-207.5f, t10, 207.5f));
        const float xf = (float)xx;
        const float ix = fmaf(t00, xf, Cx);
        const float iy = fmaf(t10, xf, Cy);

        float fx0 = floorf(ix), fy0 = floorf(iy);
        int   x0  = (int)fx0,   y0  = (int)fy0;
        float wx1 = ix - fx0,   wy1 = iy - fy0;
        float wx0 = 1.0f - wx1, wy0 = 1.0f - wy1;

        bool vx0 = (x0 >= 0)  && (x0 < IMG_W);
        bool vx1 = (x0 >= -1) && (x0 < IMG_W - 1);
        bool vy0 = (y0 >= 0)  && (y0 < IMG_H);
        bool vy1 = (y0 >= -1) && (y0 < IMG_H - 1);

        float w00 = (vx0 && vy0) ? wx0 * wy0 : 0.0f;
        float w10 = (vx1 && vy0) ? wx1 * wy0 : 0.0f;
        float w01 = (vx0 && vy1) ? wx0 * wy1 : 0.0f;
        float w11 = (vx1 && vy1) ? wx1 * wy1 : 0.0f;

        float a0 = 0.f, a1 = 0.f, a2 = 0.f;
        int i00 = y0 * IMG_W + x0;
        if (w00 != 0.0f) {
            a0 = fmaf(w00, __ldg(base + i00), a0);
            a1 = fmaf(w00, __ldg(base + cs + i00), a1);
            a2 = fmaf(w00, __ldg(base + 2 * cs + i00), a2);
        }
        if (w10 != 0.0f) {
            int i = i00 + 1;
            a0 = fmaf(w10, __ldg(base + i), a0);
            a1 = fmaf(w10, __ldg(base + cs + i), a1);
            a2 = fmaf(w10, __ldg(base + 2 * cs + i), a2);
        }
        if (w01 != 0.0f) {
            int i = i00 + IMG_W;
            a0 = fmaf(w01, __ldg(base + i), a0);
            a1 = fmaf(w01, __ldg(base + cs + i), a1);
            a2 = fmaf(w01, __ldg(base + 2 * cs + i), a2);
        }
        if (w11 != 0.0f) {
            int i = i00 + IMG_W + 1;
            a0 = fmaf(w11, __ldg(base + i), a0);
            a1 = fmaf(w11, __ldg(base + cs + i), a1);
            a2 = fmaf(w11, __ldg(base + 2 * cs + i), a2);
        }

        const int o = yy * IMG_W + xx;
        obase[o]          = a0;
        obase[o + cs]     = a1;
        obase[o + 2 * cs] = a2;
    }
}

extern "C" void kernel_launch(void* const* d_in, const int* in_sizes, int n_in,
                              void* d_out, int out_size) {
    const float* img = (const float*)d_in[0];   // adv_patch_batch (B,L,C,H,W) f32
    const float* bb  = (const float*)d_in[1];   // bboxes_batch (B,L,6) f32
    const float* ang = (const float*)d_in[2];   // angle (B*L,) f32
    const int*   pos = (n_in > 3) ? (const int*)d_in[3] : nullptr;

    int N = in_sizes[2];                        // B*L = 128

    int n4 = out_size / 4;                      // out_size divisible by 4
    fill_kernel<<<4096, TPB>>>((float4*)d_out, n4);
    patch_kernel<<<N, TPB>>>(img, bb, ang, pos, (float*)d_out);
}

// round 5
// speedup vs baseline: 1.2175x; 1.2175x over previous
#include <cuda_runtime.h>
#include <cuda_bf16.h>

#define IMG_W 416
#define IMG_H 416
#define NCH   3
#define TPB   256
#define STRIPS 32
#define SROWS  13                    // 416 / 32
#define QROW   104                   // float4 quads per row
#define CS     (IMG_W * IMG_H)       // 173056
#define CS4    (CS / 4)              // 43264
#define FILL_Q (NCH * SROWS * QROW)  // 4056 float4 per block

__global__ void __launch_bounds__(TPB)
fused_kernel(const float* __restrict__ img,
             const float* __restrict__ bb,
             const float* __restrict__ angle,
             const int*   __restrict__ pos_ptr,
             float* __restrict__ out) {
    __shared__ float th[6];
    __shared__ int   box[4];   // bx, by, bw, bh

    const int strip = blockIdx.x;
    const int n     = blockIdx.y;
    const int y0s   = strip * SROWS;

    if (threadIdx.x == 0) {
        float patch_ori = 300.0f;
        if (pos_ptr) {
            int pi = pos_ptr[0];
            patch_ori = (pi > 0 && pi < 1000000) ? (float)pi : __int_as_float(pi);
        }
        float x1 = bb[n * 6 + 0];
        float y1 = bb[n * 6 + 1];
        float x2 = bb[n * 6 + 2];
        float y2 = bb[n * 6 + 3];

        float bwv = (x2 - x1) * (float)IMG_W;
        float bhv = (y2 - y1) * (float)IMG_H;
        float cx  = (x1 + x2) * 0.5f;
        float cy  = (y1 + y2) * 0.5f - (y2 - y1) * 0.1f;
        float tx  = (0.5f - cx) * 2.0f;
        float ty  = (0.5f - cy) * 2.0f;
        float target = 0.2f * sqrtf(bwv * bwv + bhv * bhv);
        float scale  = __fdiv_rn(target, patch_ori);

        float a = angle[n];
        float s = sinf(a);
        float c = cosf(a);

        float t00 = __fdiv_rn(c, scale);
        float t01 = __fdiv_rn(s, scale);
        float t02 = __fdiv_rn(tx * c + ty * s, scale);
        float t10 = __fdiv_rn(-s, scale);
        float t11 = __fdiv_rn(c, scale);
        float t12 = __fdiv_rn(-tx * s + ty * c, scale);
        th[0] = t00; th[1] = t01; th[2] = t02;
        th[3] = t10; th[4] = t11; th[5] = t12;

        // Pixel-space map: ix = t00*x + t01*y + cx2 ; iy = t10*x + t11*y + cy2
        float cx2 = 207.5f - 207.5f * t00 - 207.5f * t01 + 208.0f * t02;
        float cy2 = 207.5f - 207.5f * t10 - 207.5f * t11 + 208.0f * t12;

        // Output-space bbox = preimage of source square [-1,416]^2
        float det  = t00 * t11 - t01 * t10;
        float rdet = __fdiv_rn(1.0f, det);
        float xmin = 1e9f, xmax = -1e9f, ymin = 1e9f, ymax = -1e9f;
#pragma unroll
        for (int k = 0; k < 4; k++) {
            float u  = (k & 1) ? 416.0f : -1.0f;
            float v  = (k & 2) ? 416.0f : -1.0f;
            float du = u - cx2;
            float dv = v - cy2;
            float px = (t11 * du - t01 * dv) * rdet;
            float py = (t00 * dv - t10 * du) * rdet;
            xmin = fminf(xmin, px); xmax = fmaxf(xmax, px);
            ymin = fminf(ymin, py); ymax = fmaxf(ymax, py);
        }
        int bx0 = max(0, (int)floorf(xmin) - 2);
        int by0 = max(0, (int)floorf(ymin) - 2);
        int bx1 = min(IMG_W - 1, (int)ceilf(xmax) + 2);
        int by1 = min(IMG_H - 1, (int)ceilf(ymax) + 2);
        box[0] = bx0;
        box[1] = by0;
        box[2] = (bx1 >= bx0) ? (bx1 - bx0 + 1) : 0;
        box[3] = (by1 >= by0) ? (by1 - by0 + 1) : 0;
    }
    __syncthreads();

    float4* obase4 = (float4*)(out + (size_t)n * NCH * CS);

    // ---- Phase 1: zero-fill this block's 13 rows x 3 channels ----
    {
        const float4 z = make_float4(0.f, 0.f, 0.f, 0.f);
        for (int f = threadIdx.x; f < FILL_Q; f += TPB) {
            int c   = f / (SROWS * QROW);
            int rem = f - c * (SROWS * QROW);
            int r   = rem / QROW;
            int q   = rem - r * QROW;
            obase4[c * CS4 + (y0s + r) * QROW + q] = z;
        }
    }

    // ---- Phase 2: bilinear-sample bbox pixels inside this strip ----
    const int bx = box[0], by = box[1], bwid = box[2], bhgt = box[3];
    const int ys = max(by, y0s);
    const int ye = min(by + bhgt - 1, y0s + SROWS - 1);
    if (ys > ye || bwid == 0) return;

    __syncthreads();   // fill of bbox pixels must land before overwrite

    const float t00 = th[0], t01 = th[1], t02 = th[2];
    const float t10 = th[3], t11 = th[4], t12 = th[5];

    const float* base = img + (size_t)n * NCH * CS;
    float* obase = out + (size_t)n * NCH * CS;

    const int nrows = ye - ys + 1;
    const int total = nrows * bwid;

    for (int idx = threadIdx.x; idx < total; idx += TPB) {
        const int rr = idx / bwid;
        const int xx = bx + (idx - rr * bwid);
        const int yy = ys + rr;

        const float ysv = __fdiv_rn(2.0f * (float)yy + 1.0f, (float)IMG_W) - 1.0f;
        const float Cx = fmaf(208.0f, fmaf(t01, ysv, t02), fmaf(-207.5f, t00, 207.5f));
        const float Cy = fmaf(208.0f, fmaf(t11, ysv, t12), fmaf(-207.5f, t10, 207.5f));
        const float xf = (float)xx;
        const float ix = fmaf(t00, xf, Cx);
        const float iy = fmaf(t10, xf, Cy);

        float fx0 = floorf(ix), fy0 = floorf(iy);
        int   x0  = (int)fx0,   y0  = (int)fy0;
        float wx1 = ix - fx0,   wy1 = iy - fy0;
        float wx0 = 1.0f - wx1, wy0 = 1.0f - wy1;

        bool vx0 = (x0 >= 0)  && (x0 < IMG_W);
        bool vx1 = (x0 >= -1) && (x0 < IMG_W - 1);
        bool vy0 = (y0 >= 0)  && (y0 < IMG_H);
        bool vy1 = (y0 >= -1) && (y0 < IMG_H - 1);

        float w00 = (vx0 && vy0) ? wx0 * wy0 : 0.0f;
        float w10 = (vx1 && vy0) ? wx1 * wy0 : 0.0f;
        float w01 = (vx0 && vy1) ? wx0 * wy1 : 0.0f;
        float w11 = (vx1 && vy1) ? wx1 * wy1 : 0.0f;

        float a0 = 0.f, a1 = 0.f, a2 = 0.f;
        int i00 = y0 * IMG_W + x0;
        if (w00 != 0.0f) {
            a0 = fmaf(w00, __ldg(base + i00), a0);
            a1 = fmaf(w00, __ldg(base + CS + i00), a1);
            a2 = fmaf(w00, __ldg(base + 2 * CS + i00), a2);
        }
        if (w10 != 0.0f) {
            int i = i00 + 1;
            a0 = fmaf(w10, __ldg(base + i), a0);
            a1 = fmaf(w10, __ldg(base + CS + i), a1);
            a2 = fmaf(w10, __ldg(base + 2 * CS + i), a2);
        }
        if (w01 != 0.0f) {
            int i = i00 + IMG_W;
            a0 = fmaf(w01, __ldg(base + i), a0);
            a1 = fmaf(w01, __ldg(base + CS + i), a1);
            a2 = fmaf(w01, __ldg(base + 2 * CS + i), a2);
        }
        if (w11 != 0.0f) {
            int i = i00 + IMG_W + 1;
            a0 = fmaf(w11, __ldg(base + i), a0);
            a1 = fmaf(w11, __ldg(base + CS + i), a1);
            a2 = fmaf(w11, __ldg(base + 2 * CS + i), a2);
        }

        const int o = yy * IMG_W + xx;
        obase[o]          = a0;
        obase[o + CS]     = a1;
        obase[o + 2 * CS] = a2;
    }
}

extern "C" void kernel_launch(void* const* d_in, const int* in_sizes, int n_in,
                              void* d_out, int out_size) {
    const float* img = (const float*)d_in[0];   // adv_patch_batch (B,L,C,H,W) f32
    const float* bb  = (const float*)d_in[1];   // bboxes_batch (B,L,6) f32
    const float* ang = (const float*)d_in[2];   // angle (B*L,) f32
    const int*   pos = (n_in > 3) ? (const int*)d_in[3] : nullptr;

    int N = in_sizes[2];                        // B*L = 128

    dim3 grid(STRIPS, N);
    fused_kernel<<<grid, TPB>>>(img, bb, ang, pos, (float*)d_out);
}